// round 8
// baseline (speedup 1.0000x reference)
#include <cuda_runtime.h>
#include <cuda_bf16.h>
#include <mma.h>
#include <cstdint>
#include <math.h>

using namespace nvcuda;

#define BB 32
#define TT 128
#define VV 16000
#define EE 512
#define ZZ 128
#define HH 1024
#define RR 64   // 2*B rows: [0,32)=free (stream 0), [32,64)=teacher (stream 1)
#define START_ID 1
#define NSPLIT 8     // split-K for gate GEMMs

// ---------------- device state ----------------
__device__ float g_h0[RR][HH];
__device__ float g_c0[RR][HH];
__device__ float g_h1[RR][HH];
__device__ float g_c1[RR][HH];
__device__ float g_part[NSPLIT][RR][4*HH];
__device__ float g_logits[RR][VV];
__device__ float g_lpart[RR][VV];
__device__ int   g_tok[RR];

// bf16 3-limb weight copies (precomputed once per launch)
__device__ __nv_bfloat16 g_Wg0[3][1664][4096];   // [Wx0;Wh0]
__device__ __nv_bfloat16 g_Wg1[3][2048][4096];   // [Wx1;Wh1]
__device__ __nv_bfloat16 g_Wl [3][1024][VV];     // Wout

__global__ void init_kernel() {
    int i = blockIdx.x * blockDim.x + threadIdx.x;
    if (i < RR * HH) {
        ((float*)g_h0)[i] = 0.f;
        ((float*)g_c0)[i] = 0.f;
        ((float*)g_h1)[i] = 0.f;
        ((float*)g_c1)[i] = 0.f;
    }
    if (i < RR) g_tok[i] = START_ID;
}

// ---------------- threefry2x32 (exact JAX semantics) ----------------
__host__ __device__ __forceinline__ uint32_t rotl32(uint32_t v, int d) {
    return (v << d) | (v >> (32 - d));
}
__host__ __device__ __forceinline__ void threefry2x32(
    uint32_t k0, uint32_t k1, uint32_t x0, uint32_t x1, uint32_t* o0, uint32_t* o1)
{
    uint32_t ks2 = k0 ^ k1 ^ 0x1BD11BDAu;
    x0 += k0; x1 += k1;
#define TF_RND(R_) { x0 += x1; x1 = rotl32(x1, R_); x1 ^= x0; }
    TF_RND(13) TF_RND(15) TF_RND(26) TF_RND(6)
    x0 += k1;  x1 += ks2 + 1u;
    TF_RND(17) TF_RND(29) TF_RND(16) TF_RND(24)
    x0 += ks2; x1 += k0 + 2u;
    TF_RND(13) TF_RND(15) TF_RND(26) TF_RND(6)
    x0 += k0;  x1 += k1 + 3u;
    TF_RND(17) TF_RND(29) TF_RND(16) TF_RND(24)
    x0 += k1;  x1 += ks2 + 4u;
    TF_RND(13) TF_RND(15) TF_RND(26) TF_RND(6)
    x0 += ks2; x1 += k0 + 5u;
#undef TF_RND
    *o0 = x0; *o1 = x1;
}
static void h_fold(uint32_t k0, uint32_t k1, uint32_t d, uint32_t* o0, uint32_t* o1) {
    threefry2x32(k0, k1, 0u, d, o0, o1);
}
__device__ __forceinline__ float jax_gumbel(uint32_t k0, uint32_t k1, uint32_t idx) {
    uint32_t o0, o1;
    threefry2x32(k0, k1, 0u, idx, &o0, &o1);
    uint32_t bits = o0 ^ o1;
    float f = __uint_as_float((bits >> 9) | 0x3f800000u) - 1.0f;
    float u = fmaxf(f, 1.17549435e-38f);
    return -logf(-logf(u));
}

// ---------------- fp32 -> 3 bf16 limbs ----------------
__device__ __forceinline__ void split3(float a, __nv_bfloat16& h, __nv_bfloat16& l,
                                       __nv_bfloat16& m) {
    h = __float2bfloat16(a);
    float r1 = a - __bfloat162float(h);
    l = __float2bfloat16(r1);
    m = __float2bfloat16(r1 - __bfloat162float(l));
}

// ---------------- weight limb precompute (once per launch) ----------------
__global__ void prep_kernel(const float* __restrict__ Wx0, const float* __restrict__ Wh0,
                            const float* __restrict__ Wx1, const float* __restrict__ Wh1,
                            const float* __restrict__ Wout)
{
    int stride = gridDim.x * blockDim.x;
    int t0 = blockIdx.x * blockDim.x + threadIdx.x;
    for (int i = t0; i < 1664 * 4096; i += stride) {
        int k = i >> 12, n = i & 4095;
        float v = (k < 640) ? Wx0[(size_t)k * 4096 + n] : Wh0[(size_t)(k - 640) * 4096 + n];
        __nv_bfloat16 h, l, m; split3(v, h, l, m);
        g_Wg0[0][k][n] = h; g_Wg0[1][k][n] = l; g_Wg0[2][k][n] = m;
    }
    for (int i = t0; i < 2048 * 4096; i += stride) {
        int k = i >> 12, n = i & 4095;
        float v = (k < 1024) ? Wx1[(size_t)k * 4096 + n] : Wh1[(size_t)(k - 1024) * 4096 + n];
        __nv_bfloat16 h, l, m; split3(v, h, l, m);
        g_Wg1[0][k][n] = h; g_Wg1[1][k][n] = l; g_Wg1[2][k][n] = m;
    }
    for (int i = t0; i < 1024 * VV; i += stride) {
        int k = i / VV, n = i - k * VV;
        float v = Wout[(size_t)k * VV + n];
        __nv_bfloat16 h, l, m; split3(v, h, l, m);
        g_Wl[0][k][n] = h; g_Wl[1][k][n] = l; g_Wl[2][k][n] = m;
    }
}

// ---------------- A-gather and B-row helpers ----------------
template<int MODE>
__device__ __forceinline__ float gatherA(int r, int k, const float* __restrict__ emb,
                                         const float* __restrict__ z, const int* toks) {
    if (MODE == 0) {
        if (k < 512)  return emb[(size_t)toks[r] * EE + k];
        if (k < 640)  return z[(size_t)(r & 31) * ZZ + (k - 512)];
        return g_h0[r][k - 640];
    } else if (MODE == 1) {
        return (k < 1024) ? g_h0[r][k] : g_h1[r][k - 1024];
    } else {
        return g_h1[r][k];
    }
}
template<int MODE>
__device__ __forceinline__ const __nv_bfloat16* bptr(int l, int k) {
    if (MODE == 0)      return &g_Wg0[l][k][0];
    else if (MODE == 1) return &g_Wg1[l][k][0];
    else                return &g_Wl[l][k][0];
}

// ---------------- tensor GEMM via wmma bf16x6 -------------------------------
// C[64, Ntile=128] += A[64,Kslice] * B[Kslice,128], fp32-faithful via 3-limb bf16.
// MODE 0: gates L0 (K=1664, split 8) -> g_part[by]
// MODE 1: gates L1 (K=2048, split 8) -> g_part[by]
// MODE 2: logits   (K=1024, split 2) -> g_logits / g_lpart (bias added in sample)
template<int MODE>
__global__ __launch_bounds__(128) void tgemm(const float* __restrict__ emb,
                                             const float* __restrict__ z)
{
    constexpr int KTOT = (MODE == 0) ? 1664 : ((MODE == 1) ? 2048 : 1024);
    constexpr int KSL  = (MODE == 2) ? 2 : NSPLIT;
    constexpr int KS   = KTOT / KSL;       // 208 / 256 / 512
    constexpr int NK16 = KS / 16;          // 13 / 16 / 32

    __shared__ __nv_bfloat16 As[3][64][16];
    __shared__ __nv_bfloat16 Bs[3][16][128];
    __shared__ int toks[64];

    const int tid = threadIdx.x, wid = tid >> 5;
    const int warp_m = wid & 1, warp_n = wid >> 1;
    const int n0 = blockIdx.x * 128, kb0 = blockIdx.y * KS;
    const int r = tid >> 1, half = tid & 1;

    if (MODE == 0 && tid < 64) toks[tid] = g_tok[tid];
    __syncthreads();

    wmma::fragment<wmma::accumulator, 16, 16, 16, float> acc[2][4];
#pragma unroll
    for (int mt = 0; mt < 2; mt++)
#pragma unroll
        for (int nt = 0; nt < 4; nt++) wmma::fill_fragment(acc[mt][nt], 0.f);

    float av[8];
    uint4 bv[6];

#define GLOAD(kb_) do { \
    _Pragma("unroll") \
    for (int e = 0; e < 8; e++) av[e] = gatherA<MODE>(r, (kb_) + half * 8 + e, emb, z, toks); \
    _Pragma("unroll") \
    for (int i = 0; i < 6; i++) { \
        int idx = tid + i * 128; int l = idx >> 8; int kk = (idx >> 4) & 15; int q = idx & 15; \
        bv[i] = *(const uint4*)(bptr<MODE>(l, (kb_) + kk) + n0 + q * 8); \
    } } while (0)

#define SSTORE() do { \
    ushort hs[8], ls[8], ms[8]; \
    _Pragma("unroll") \
    for (int e = 0; e < 8; e++) { \
        __nv_bfloat16 h_, l_, m_; split3(av[e], h_, l_, m_); \
        hs[e] = __bfloat16_as_ushort(h_); ls[e] = __bfloat16_as_ushort(l_); \
        ms[e] = __bfloat16_as_ushort(m_); \
    } \
    *(uint4*)&As[0][r][half * 8] = make_uint4( \
        (uint32_t)hs[0] | ((uint32_t)hs[1] << 16), (uint32_t)hs[2] | ((uint32_t)hs[3] << 16), \
        (uint32_t)hs[4] | ((uint32_t)hs[5] << 16), (uint32_t)hs[6] | ((uint32_t)hs[7] << 16)); \
    *(uint4*)&As[1][r][half * 8] = make_uint4( \
        (uint32_t)ls[0] | ((uint32_t)ls[1] << 16), (uint32_t)ls[2] | ((uint32_t)ls[3] << 16), \
        (uint32_t)ls[4] | ((uint32_t)ls[5] << 16), (uint32_t)ls[6] | ((uint32_t)ls[7] << 16)); \
    *(uint4*)&As[2][r][half * 8] = make_uint4( \
        (uint32_t)ms[0] | ((uint32_t)ms[1] << 16), (uint32_t)ms[2] | ((uint32_t)ms[3] << 16), \
        (uint32_t)ms[4] | ((uint32_t)ms[5] << 16), (uint32_t)ms[6] | ((uint32_t)ms[7] << 16)); \
    _Pragma("unroll") \
    for (int i = 0; i < 6; i++) { \
        int idx = tid + i * 128; int l = idx >> 8; int kk = (idx >> 4) & 15; int q = idx & 15; \
        *(uint4*)&Bs[l][kk][q * 8] = bv[i]; \
    } } while (0)

    GLOAD(kb0);
    SSTORE();
    __syncthreads();

    for (int s = 0; s < NK16; s++) {
        if (s + 1 < NK16) GLOAD(kb0 + (s + 1) * 16);

        wmma::fragment<wmma::matrix_a, 16, 16, 16, __nv_bfloat16, wmma::row_major> af[3][2];
#pragma unroll
        for (int l = 0; l < 3; l++)
#pragma unroll
            for (int mt = 0; mt < 2; mt++)
                wmma::load_matrix_sync(af[l][mt], &As[l][warp_m * 32 + mt * 16][0], 16);

#pragma unroll
        for (int lb = 0; lb < 3; lb++) {
            wmma::fragment<wmma::matrix_b, 16, 16, 16, __nv_bfloat16, wmma::row_major> bf[4];
#pragma unroll
            for (int nt = 0; nt < 4; nt++)
                wmma::load_matrix_sync(bf[nt], &Bs[lb][0][warp_n * 64 + nt * 16], 128);
            // limb pairs: (0,0),(0,1),(1,0),(0,2),(1,1),(2,0) grouped by lb
#pragma unroll
            for (int la = 0; la < 3 - lb; la++)
#pragma unroll
                for (int mt = 0; mt < 2; mt++)
#pragma unroll
                    for (int nt = 0; nt < 4; nt++)
                        wmma::mma_sync(acc[mt][nt], af[la][mt], bf[nt], acc[mt][nt]);
        }
        __syncthreads();
        if (s + 1 < NK16) SSTORE();
        __syncthreads();
    }

    // ---- epilogue ----
    float* Cp;
    int ld;
    if (MODE == 2) {
        Cp = (blockIdx.y == 0) ? &g_logits[0][0] : &g_lpart[0][0];
        ld = VV;
    } else {
        Cp = &g_part[blockIdx.y][0][0];
        ld = 4096;
    }
#pragma unroll
    for (int mt = 0; mt < 2; mt++)
#pragma unroll
        for (int nt = 0; nt < 4; nt++)
            wmma::store_matrix_sync(
                Cp + (size_t)(warp_m * 32 + mt * 16) * ld + n0 + warp_n * 64 + nt * 16,
                acc[mt][nt], ld, wmma::mem_row_major);
#undef GLOAD
#undef SSTORE
}

// ---------------- LSTM cell: fused split-K reduce + bias + cell --------------
__device__ __forceinline__ float sigf(float x) { return 1.f / (1.f + expf(-x)); }

__global__ void cell_kernel(int layer, const float* __restrict__ bias) {
    int idx4 = blockIdx.x * blockDim.x + threadIdx.x;
    if (idx4 >= RR * HH / 4) return;
    int r = idx4 >> 8;
    int j = (idx4 & 255) * 4;
    float* hA = layer ? &g_h1[0][0] : &g_h0[0][0];
    float* cA = layer ? &g_c1[0][0] : &g_c0[0][0];

    float4 gi = *reinterpret_cast<const float4*>(bias + j);
    float4 gf = *reinterpret_cast<const float4*>(bias + j + HH);
    float4 gg = *reinterpret_cast<const float4*>(bias + j + 2 * HH);
    float4 go = *reinterpret_cast<const float4*>(bias + j + 3 * HH);
#pragma unroll
    for (int s = 0; s < NSPLIT; s++) {
        float4 a = *reinterpret_cast<const float4*>(&g_part[s][r][j]);
        float4 b = *reinterpret_cast<const float4*>(&g_part[s][r][j + HH]);
        float4 c = *reinterpret_cast<const float4*>(&g_part[s][r][j + 2 * HH]);
        float4 d = *reinterpret_cast<const float4*>(&g_part[s][r][j + 3 * HH]);
        gi.x += a.x; gi.y += a.y; gi.z += a.z; gi.w += a.w;
        gf.x += b.x; gf.y += b.y; gf.z += b.z; gf.w += b.w;
        gg.x += c.x; gg.y += c.y; gg.z += c.z; gg.w += c.w;
        go.x += d.x; go.y += d.y; go.z += d.z; go.w += d.w;
    }
    float4 cc = *reinterpret_cast<const float4*>(cA + (size_t)r * HH + j);
    float4 hh;
    cc.x = sigf(gf.x) * cc.x + sigf(gi.x) * tanhf(gg.x);
    cc.y = sigf(gf.y) * cc.y + sigf(gi.y) * tanhf(gg.y);
    cc.z = sigf(gf.z) * cc.z + sigf(gi.z) * tanhf(gg.z);
    cc.w = sigf(gf.w) * cc.w + sigf(gi.w) * tanhf(gg.w);
    hh.x = sigf(go.x) * tanhf(cc.x);
    hh.y = sigf(go.y) * tanhf(cc.y);
    hh.z = sigf(go.z) * tanhf(cc.z);
    hh.w = sigf(go.w) * tanhf(cc.w);
    *reinterpret_cast<float4*>(cA + (size_t)r * HH + j) = cc;
    *reinterpret_cast<float4*>(hA + (size_t)r * HH + j) = hh;
}

// ---------------- softmax + p output + gumbel argmax sampling ----------------
// Fuses logits split-K reduce AND the output bias: L = part0 + part1 + bout.
#define STH 512
__global__ __launch_bounds__(STH) void sample_kernel(
    int t, uint32_t k0s0, uint32_t k1s0, uint32_t k0s1, uint32_t k1s1,
    const int* __restrict__ x, const float* __restrict__ bout,
    float* __restrict__ out)
{
    const int r   = blockIdx.x;
    const int tid = threadIdx.x;
    const int stream = (r < BB) ? 0 : 1;
    const int b   = r & 31;
    float4* L4  = reinterpret_cast<float4*>(&g_logits[r][0]);
    const float4* P4 = reinterpret_cast<const float4*>(&g_lpart[r][0]);
    const float4* B4 = reinterpret_cast<const float4*>(bout);
    constexpr int NV4 = VV / 4;

    __shared__ float red[STH];
    __shared__ int   redi[STH];

    float m = -INFINITY;
    for (int v4 = tid; v4 < NV4; v4 += STH) {
        float4 a = L4[v4];
        float4 p = P4[v4];
        float4 bb = B4[v4];
        a.x += p.x + bb.x; a.y += p.y + bb.y; a.z += p.z + bb.z; a.w += p.w + bb.w;
        L4[v4] = a;
        m = fmaxf(m, fmaxf(fmaxf(a.x, a.y), fmaxf(a.z, a.w)));
    }
    red[tid] = m; __syncthreads();
    for (int s = STH / 2; s > 0; s >>= 1) {
        if (tid < s) red[tid] = fmaxf(red[tid], red[tid + s]);
        __syncthreads();
    }
    m = red[0]; __syncthreads();

    float sum = 0.f;
    for (int v4 = tid; v4 < NV4; v4 += STH) {
        float4 a = L4[v4];
        sum += expf(a.x - m) + expf(a.y - m) + expf(a.z - m) + expf(a.w - m);
    }
    red[tid] = sum; __syncthreads();
    for (int s = STH / 2; s > 0; s >>= 1) {
        if (tid < s) red[tid] += red[tid + s];
        __syncthreads();
    }
    float lse = logf(red[0]); __syncthreads();

    const uint32_t k0 = stream ? k0s1 : k0s0;
    const uint32_t k1 = stream ? k1s1 : k1s0;
    const size_t p_off = stream ? ((size_t)4096 + (size_t)BB * TT * VV + 4096)
                                : (size_t)4096;
    const size_t pbase = p_off + ((size_t)b * TT + t) * VV;
    float4* O4 = reinterpret_cast<float4*>(out + pbase);

    float best = -INFINITY; int bidx = VV;
    for (int v4 = tid; v4 < NV4; v4 += STH) {
        float4 a = L4[v4];
        float lp[4] = {a.x - m - lse, a.y - m - lse, a.z - m - lse, a.w - m - lse};
        float4 pw;
        pw.x = expf(lp[0]); pw.y = expf(lp[1]); pw.z = expf(lp[2]); pw.w = expf(lp[3]);
        O4[v4] = pw;
#pragma unroll
        for (int e = 0; e < 4; e++) {
            int v = v4 * 4 + e;
            float g = jax_gumbel(k0, k1, (uint32_t)(b * VV + v));
            float sc = lp[e] + g;
            if (sc > best) { best = sc; bidx = v; }
        }
    }
    red[tid] = best; redi[tid] = bidx; __syncthreads();
    for (int s = STH / 2; s > 0; s >>= 1) {
        if (tid < s) {
            float o = red[tid + s]; int oi = redi[tid + s];
            if (o > red[tid] || (o == red[tid] && oi < redi[tid])) {
                red[tid] = o; redi[tid] = oi;
            }
        }
        __syncthreads();
    }
    if (tid == 0) {
        int am = redi[0];
        size_t sbase = stream ? ((size_t)4096 + (size_t)BB * TT * VV) : (size_t)0;
        out[sbase + (size_t)b * TT + t] = (float)am;
        g_tok[r] = stream ? x[(size_t)b * TT + t] : am;
    }
}

// ---------------- host driver ----------------
extern "C" void kernel_launch(void* const* d_in, const int* in_sizes, int n_in,
                              void* d_out, int out_size)
{
    const int*   x    = (const int*)  d_in[0];
    const float* z    = (const float*)d_in[1];
    const float* emb  = (const float*)d_in[2];
    const float* Wx0  = (const float*)d_in[3];
    const float* Wh0  = (const float*)d_in[4];
    const float* b0   = (const float*)d_in[5];
    const float* Wx1  = (const float*)d_in[6];
    const float* Wh1  = (const float*)d_in[7];
    const float* b1   = (const float*)d_in[8];
    const float* Wout = (const float*)d_in[9];
    const float* bout = (const float*)d_in[10];
    float* out = (float*)d_out;

    init_kernel<<<256, 256>>>();
    prep_kernel<<<1024, 256>>>(Wx0, Wh0, Wx1, Wh1, Wout);

    uint32_t s0a, s0b, s1a, s1b;
    h_fold(0u, 42u, 0u, &s0a, &s0b);
    h_fold(0u, 42u, 1u, &s1a, &s1b);

    for (int t = 0; t < TT; t++) {
        uint32_t k0s0, k1s0, k0s1, k1s1;
        h_fold(s0a, s0b, (uint32_t)t, &k0s0, &k1s0);
        h_fold(s1a, s1b, (uint32_t)t, &k0s1, &k1s1);

        tgemm<0><<<dim3(32, NSPLIT), 128>>>(emb, z);
        cell_kernel<<<(RR * HH / 4 + 255) / 256, 256>>>(0, b0);
        tgemm<1><<<dim3(32, NSPLIT), 128>>>(emb, z);
        cell_kernel<<<(RR * HH / 4 + 255) / 256, 256>>>(1, b1);
        tgemm<2><<<dim3(125, 2), 128>>>(emb, z);
        sample_kernel<<<RR, STH>>>(t, k0s0, k1s0, k0s1, k1s1, x, bout, out);
    }
}

// round 10
// speedup vs baseline: 1.3897x; 1.3897x over previous
#include <cuda_runtime.h>
#include <cstdint>
#include <math.h>

#define BB 32
#define TT 128
#define VV 16000
#define EE 512
#define ZZ 128
#define HH 1024
#define RR 64   // 2*B rows: [0,32)=free-running (stream 0), [32,64)=teacher (stream 1)
#define START_ID 1
#define NSPLIT 8      // split-K for gate GEMMs

// ---------------- device state ----------------
__device__ float g_h0[RR][HH];
__device__ float g_c0[RR][HH];
__device__ float g_h1[RR][HH];
__device__ float g_c1[RR][HH];
__device__ float g_part[NSPLIT][RR][4*HH];   // split-K partials for gate GEMMs
__device__ float g_logits[RR][VV];
__device__ float g_lpart[RR][VV];            // split-K partial for logits GEMM
__device__ float g_zb0[BB][4*HH];            // z @ Wx0[512:640] + b0 (step-invariant)
__device__ int   g_tok[RR];

// ---------------- init ----------------
__global__ void init_kernel() {
    int i = blockIdx.x * blockDim.x + threadIdx.x;
    if (i < RR * HH) {
        ((float*)g_h0)[i] = 0.f;
        ((float*)g_c0)[i] = 0.f;
        ((float*)g_h1)[i] = 0.f;
        ((float*)g_c1)[i] = 0.f;
    }
    if (i < RR) g_tok[i] = START_ID;
}

// zb0[b][n] = sum_k z[b][k] * Wx0[512+k][n] + b0[n]   (once per launch)
__global__ void zb0_kernel(const float* __restrict__ z, const float* __restrict__ Wx0,
                           const float* __restrict__ b0) {
    int idx = blockIdx.x * blockDim.x + threadIdx.x;   // 32*4096
    if (idx >= BB * 4 * HH) return;
    int b = idx >> 12, n = idx & 4095;
    float s = b0[n];
    for (int k = 0; k < ZZ; k++)
        s += z[b * ZZ + k] * Wx0[(size_t)(512 + k) * 4096 + n];
    g_zb0[b][n] = s;
}

// ---------------- threefry2x32 (exact JAX semantics) ----------------
__host__ __device__ __forceinline__ uint32_t rotl32(uint32_t v, int d) {
    return (v << d) | (v >> (32 - d));
}
__host__ __device__ __forceinline__ void threefry2x32(
    uint32_t k0, uint32_t k1, uint32_t x0, uint32_t x1, uint32_t* o0, uint32_t* o1)
{
    uint32_t ks2 = k0 ^ k1 ^ 0x1BD11BDAu;
    x0 += k0; x1 += k1;
#define TF_RND(R_) { x0 += x1; x1 = rotl32(x1, R_); x1 ^= x0; }
    TF_RND(13) TF_RND(15) TF_RND(26) TF_RND(6)
    x0 += k1;  x1 += ks2 + 1u;
    TF_RND(17) TF_RND(29) TF_RND(16) TF_RND(24)
    x0 += ks2; x1 += k0 + 2u;
    TF_RND(13) TF_RND(15) TF_RND(26) TF_RND(6)
    x0 += k0;  x1 += k1 + 3u;
    TF_RND(17) TF_RND(29) TF_RND(16) TF_RND(24)
    x0 += k1;  x1 += ks2 + 4u;
    TF_RND(13) TF_RND(15) TF_RND(26) TF_RND(6)
    x0 += ks2; x1 += k0 + 5u;
#undef TF_RND
    *o0 = x0; *o1 = x1;
}
static void h_fold(uint32_t k0, uint32_t k1, uint32_t d, uint32_t* o0, uint32_t* o1) {
    threefry2x32(k0, k1, 0u, d, o0, o1);
}
// JAX >= 0.4.30 partitionable threefry: counter = u64(idx) -> (0, idx), bits = o0^o1
__device__ __forceinline__ float jax_gumbel(uint32_t k0, uint32_t k1, uint32_t idx) {
    uint32_t o0, o1;
    threefry2x32(k0, k1, 0u, idx, &o0, &o1);
    uint32_t bits = o0 ^ o1;
    float f = __uint_as_float((bits >> 9) | 0x3f800000u) - 1.0f;
    float u = fmaxf(f, 1.17549435e-38f);
    return -logf(-logf(u));
}

// ---------------- GEMM: M=64, BN=128, Kc=32, 256 thr, 8x4/thread, dbuf smem ----
// MODE 0: gates L0, K=1536 (8 slices of 192), A=[emb[tok]|h0], B=[Wx0(0:512);Wh0]
// MODE 1: gates L1, K=2048 (8 slices of 256), A=[h0|h1],       B=[Wx1;Wh1]
// MODE 2: logits,   K=1024 (2 slices of 512), A=h1,            B=Wout (+bias on y0)
template<int MODE>
__device__ __forceinline__ void load_tile(
    int k0, int rA, int kkA, int kkB, int nnB, int n0,
    const float* __restrict__ emb,
    const float* __restrict__ W1,  const float* __restrict__ W2,
    const int* toks, float pa[8], float4 pb[4])
{
#pragma unroll
    for (int e = 0; e < 8; e++) {
        int k = k0 + kkA + e;
        float v;
        if (MODE == 0) {
            v = (k < 512) ? emb[(size_t)toks[rA] * EE + k] : g_h0[rA][k - 512];
        } else if (MODE == 1) {
            v = (k < 1024) ? g_h0[rA][k] : g_h1[rA][k - 1024];
        } else {
            v = g_h1[rA][k];
        }
        pa[e] = v;
    }
    {
        int k = k0 + kkB;
        const float* row;
        if (MODE == 0)      row = (k < 512)  ? (W1 + (size_t)k * 4096)
                                             : (W2 + (size_t)(k - 512) * 4096);
        else if (MODE == 1) row = (k < 1024) ? (W1 + (size_t)k * 4096)
                                             : (W2 + (size_t)(k - 1024) * 4096);
        else                row = W1 + (size_t)k * VV;
#pragma unroll
        for (int q = 0; q < 4; q++)
            pb[q] = *reinterpret_cast<const float4*>(row + n0 + nnB + 4 * q);
    }
}

template<int MODE>
__global__ __launch_bounds__(256) void gemm_kernel(
    const float* __restrict__ emb,
    const float* __restrict__ W1,  const float* __restrict__ W2,
    const float* __restrict__ bias)
{
    constexpr int KTOT = (MODE == 0) ? 1536 : ((MODE == 1) ? 2048 : 1024);
    constexpr int KSL  = (MODE == 2) ? 2 : NSPLIT;
    constexpr int KS   = KTOT / KSL;     // 192 / 256 / 512

    __shared__ float As[2][32][64];
    __shared__ float Bs[2][32][128];
    __shared__ int   toks[64];

    const int tid = threadIdx.x;
    const int n0  = blockIdx.x * 128;
    const int ks0 = blockIdx.y * KS;
    const int tx  = tid & 31;
    const int ty  = tid >> 5;
    const int rA  = tid >> 2;          // A: 64 rows, 4 thr/row
    const int kkA = (tid & 3) * 8;     // 8 consecutive k
    const int kkB = tid >> 3;          // B: 32 k-rows, 8 thr/row
    const int nnB = (tid & 7) * 16;    // 16 consecutive n

    if (MODE == 0) {
        if (tid < 64) toks[tid] = g_tok[tid];
        __syncthreads();
    }

    float acc[8][4];
#pragma unroll
    for (int i = 0; i < 8; i++)
#pragma unroll
        for (int j = 0; j < 4; j++) acc[i][j] = 0.f;

    float pa[8]; float4 pb[4];

    load_tile<MODE>(ks0, rA, kkA, kkB, nnB, n0, emb, W1, W2, toks, pa, pb);
    {
#pragma unroll
        for (int e = 0; e < 8; e++) As[0][kkA + e][rA] = pa[e];
#pragma unroll
        for (int q = 0; q < 4; q++)
            *reinterpret_cast<float4*>(&Bs[0][kkB][nnB + 4 * q]) = pb[q];
    }
    __syncthreads();

    int buf = 0;
    for (int k0 = ks0; k0 < ks0 + KS; k0 += 32) {
        const bool more = (k0 + 32) < (ks0 + KS);
        if (more)
            load_tile<MODE>(k0 + 32, rA, kkA, kkB, nnB, n0, emb, W1, W2, toks, pa, pb);

#pragma unroll
        for (int kk = 0; kk < 32; kk++) {
            float4 a0 = *reinterpret_cast<const float4*>(&As[buf][kk][ty * 8]);
            float4 a1 = *reinterpret_cast<const float4*>(&As[buf][kk][ty * 8 + 4]);
            float4 b4 = *reinterpret_cast<const float4*>(&Bs[buf][kk][tx * 4]);
            float a[8] = {a0.x, a0.y, a0.z, a0.w, a1.x, a1.y, a1.z, a1.w};
#pragma unroll
            for (int i = 0; i < 8; i++) {
                acc[i][0] += a[i] * b4.x;
                acc[i][1] += a[i] * b4.y;
                acc[i][2] += a[i] * b4.z;
                acc[i][3] += a[i] * b4.w;
            }
        }

        if (more) {
            int nb = buf ^ 1;
#pragma unroll
            for (int e = 0; e < 8; e++) As[nb][kkA + e][rA] = pa[e];
#pragma unroll
            for (int q = 0; q < 4; q++)
                *reinterpret_cast<float4*>(&Bs[nb][kkB][nnB + 4 * q]) = pb[q];
        }
        __syncthreads();
        buf ^= 1;
    }

    // ---- epilogue ----
    const int nc = n0 + tx * 4;
    if (MODE == 2) {
        if (blockIdx.y == 0) {
            float4 bv = *reinterpret_cast<const float4*>(bias + nc);
#pragma unroll
            for (int i = 0; i < 8; i++) {
                int r = ty * 8 + i;
                float4 o;
                o.x = acc[i][0] + bv.x;
                o.y = acc[i][1] + bv.y;
                o.z = acc[i][2] + bv.z;
                o.w = acc[i][3] + bv.w;
                *reinterpret_cast<float4*>(&g_logits[0][0] + (size_t)r * VV + nc) = o;
            }
        } else {
#pragma unroll
            for (int i = 0; i < 8; i++) {
                int r = ty * 8 + i;
                float4 o;
                o.x = acc[i][0]; o.y = acc[i][1]; o.z = acc[i][2]; o.w = acc[i][3];
                *reinterpret_cast<float4*>(&g_lpart[0][0] + (size_t)r * VV + nc) = o;
            }
        }
    } else {
        float* P = &g_part[blockIdx.y][0][0];
#pragma unroll
        for (int i = 0; i < 8; i++) {
            int r = ty * 8 + i;
            float4 o;
            o.x = acc[i][0]; o.y = acc[i][1]; o.z = acc[i][2]; o.w = acc[i][3];
            *reinterpret_cast<float4*>(P + (size_t)r * 4096 + nc) = o;
        }
    }
}

// ---------------- LSTM cell: fused split-K reduce + bias/zb0 + cell ----------
__device__ __forceinline__ float sigf(float x) { return 1.f / (1.f + expf(-x)); }

__global__ void cell_kernel(int layer, const float* __restrict__ bias) {
    int idx4 = blockIdx.x * blockDim.x + threadIdx.x;
    if (idx4 >= RR * HH / 4) return;
    int r = idx4 >> 8;
    int j = (idx4 & 255) * 4;
    float* hA = layer ? &g_h1[0][0] : &g_h0[0][0];
    float* cA = layer ? &g_c1[0][0] : &g_c0[0][0];

    float4 gi, gf, gg, go;
    if (layer == 0) {
        const float* zb = &g_zb0[r & 31][0];   // z-projection + b0 (step-invariant)
        gi = *reinterpret_cast<const float4*>(zb + j);
        gf = *reinterpret_cast<const float4*>(zb + j + HH);
        gg = *reinterpret_cast<const float4*>(zb + j + 2 * HH);
        go = *reinterpret_cast<const float4*>(zb + j + 3 * HH);
    } else {
        gi = *reinterpret_cast<const float4*>(bias + j);
        gf = *reinterpret_cast<const float4*>(bias + j + HH);
        gg = *reinterpret_cast<const float4*>(bias + j + 2 * HH);
        go = *reinterpret_cast<const float4*>(bias + j + 3 * HH);
    }
#pragma unroll
    for (int s = 0; s < NSPLIT; s++) {
        float4 a = *reinterpret_cast<const float4*>(&g_part[s][r][j]);
        float4 b = *reinterpret_cast<const float4*>(&g_part[s][r][j + HH]);
        float4 c = *reinterpret_cast<const float4*>(&g_part[s][r][j + 2 * HH]);
        float4 d = *reinterpret_cast<const float4*>(&g_part[s][r][j + 3 * HH]);
        gi.x += a.x; gi.y += a.y; gi.z += a.z; gi.w += a.w;
        gf.x += b.x; gf.y += b.y; gf.z += b.z; gf.w += b.w;
        gg.x += c.x; gg.y += c.y; gg.z += c.z; gg.w += c.w;
        go.x += d.x; go.y += d.y; go.z += d.z; go.w += d.w;
    }
    float4 cc = *reinterpret_cast<const float4*>(cA + (size_t)r * HH + j);
    float4 hh;
    cc.x = sigf(gf.x) * cc.x + sigf(gi.x) * tanhf(gg.x);
    cc.y = sigf(gf.y) * cc.y + sigf(gi.y) * tanhf(gg.y);
    cc.z = sigf(gf.z) * cc.z + sigf(gi.z) * tanhf(gg.z);
    cc.w = sigf(gf.w) * cc.w + sigf(gi.w) * tanhf(gg.w);
    hh.x = sigf(go.x) * tanhf(cc.x);
    hh.y = sigf(go.y) * tanhf(cc.y);
    hh.z = sigf(go.z) * tanhf(cc.z);
    hh.w = sigf(go.w) * tanhf(cc.w);
    *reinterpret_cast<float4*>(cA + (size_t)r * HH + j) = cc;
    *reinterpret_cast<float4*>(hA + (size_t)r * HH + j) = hh;
}

// ---------------- softmax + p output + gumbel argmax sampling ----------------
// Fuses the logits split-K reduction: L = g_logits(+bias already) + g_lpart.
#define STH 512
__global__ __launch_bounds__(STH) void sample_kernel(
    int t, uint32_t k0s0, uint32_t k1s0, uint32_t k0s1, uint32_t k1s1,
    const int* __restrict__ x, float* __restrict__ out)
{
    const int r   = blockIdx.x;
    const int tid = threadIdx.x;
    const int stream = (r < BB) ? 0 : 1;
    const int b   = r & 31;
    float4* L4  = reinterpret_cast<float4*>(&g_logits[r][0]);
    const float4* P4 = reinterpret_cast<const float4*>(&g_lpart[r][0]);
    constexpr int NV4 = VV / 4;

    __shared__ float red[STH];
    __shared__ int   redi[STH];

    float m = -INFINITY;
    for (int v4 = tid; v4 < NV4; v4 += STH) {
        float4 a = L4[v4];
        float4 p = P4[v4];
        a.x += p.x; a.y += p.y; a.z += p.z; a.w += p.w;
        L4[v4] = a;
        m = fmaxf(m, fmaxf(fmaxf(a.x, a.y), fmaxf(a.z, a.w)));
    }
    red[tid] = m; __syncthreads();
    for (int s = STH / 2; s > 0; s >>= 1) {
        if (tid < s) red[tid] = fmaxf(red[tid], red[tid + s]);
        __syncthreads();
    }
    m = red[0]; __syncthreads();

    float sum = 0.f;
    for (int v4 = tid; v4 < NV4; v4 += STH) {
        float4 a = L4[v4];
        sum += expf(a.x - m) + expf(a.y - m) + expf(a.z - m) + expf(a.w - m);
    }
    red[tid] = sum; __syncthreads();
    for (int s = STH / 2; s > 0; s >>= 1) {
        if (tid < s) red[tid] += red[tid + s];
        __syncthreads();
    }
    float lse = logf(red[0]); __syncthreads();

    const uint32_t k0 = stream ? k0s1 : k0s0;
    const uint32_t k1 = stream ? k1s1 : k1s0;
    const size_t p_off = stream ? ((size_t)4096 + (size_t)BB * TT * VV + 4096)
                                : (size_t)4096;
    const size_t pbase = p_off + ((size_t)b * TT + t) * VV;
    float4* O4 = reinterpret_cast<float4*>(out + pbase);

    float best = -INFINITY; int bidx = VV;
    for (int v4 = tid; v4 < NV4; v4 += STH) {
        float4 a = L4[v4];
        float lp[4] = {a.x - m - lse, a.y - m - lse, a.z - m - lse, a.w - m - lse};
        float4 pw;
        pw.x = expf(lp[0]); pw.y = expf(lp[1]); pw.z = expf(lp[2]); pw.w = expf(lp[3]);
        O4[v4] = pw;
#pragma unroll
        for (int e = 0; e < 4; e++) {
            int v = v4 * 4 + e;
            float g = jax_gumbel(k0, k1, (uint32_t)(b * VV + v));
            float sc = lp[e] + g;
            if (sc > best) { best = sc; bidx = v; }
        }
    }
    red[tid] = best; redi[tid] = bidx; __syncthreads();
    for (int s = STH / 2; s > 0; s >>= 1) {
        if (tid < s) {
            float o = red[tid + s]; int oi = redi[tid + s];
            if (o > red[tid] || (o == red[tid] && oi < redi[tid])) {
                red[tid] = o; redi[tid] = oi;
            }
        }
        __syncthreads();
    }
    if (tid == 0) {
        int am = redi[0];
        size_t sbase = stream ? ((size_t)4096 + (size_t)BB * TT * VV) : (size_t)0;
        out[sbase + (size_t)b * TT + t] = (float)am;
        g_tok[r] = stream ? x[(size_t)b * TT + t] : am;
    }
}

// ---------------- host driver ----------------
extern "C" void kernel_launch(void* const* d_in, const int* in_sizes, int n_in,
                              void* d_out, int out_size)
{
    const int*   x    = (const int*)  d_in[0];
    const float* z    = (const float*)d_in[1];
    const float* emb  = (const float*)d_in[2];
    const float* Wx0  = (const float*)d_in[3];
    const float* Wh0  = (const float*)d_in[4];
    const float* b0   = (const float*)d_in[5];
    const float* Wx1  = (const float*)d_in[6];
    const float* Wh1  = (const float*)d_in[7];
    const float* b1   = (const float*)d_in[8];
    const float* Wout = (const float*)d_in[9];
    const float* bout = (const float*)d_in[10];
    float* out = (float*)d_out;

    init_kernel<<<256, 256>>>();
    zb0_kernel<<<(BB * 4 * HH + 255) / 256, 256>>>(z, Wx0, b0);

    uint32_t s0a, s0b, s1a, s1b;
    h_fold(0u, 42u, 0u, &s0a, &s0b);
    h_fold(0u, 42u, 1u, &s1a, &s1b);

    for (int t = 0; t < TT; t++) {
        uint32_t k0s0, k1s0, k0s1, k1s1;
        h_fold(s0a, s0b, (uint32_t)t, &k0s0, &k1s0);
        h_fold(s1a, s1b, (uint32_t)t, &k0s1, &k1s1);

        gemm_kernel<0><<<dim3(32, NSPLIT), 256>>>(emb, Wx0, Wh0, b0);
        cell_kernel<<<(RR * HH / 4 + 255) / 256, 256>>>(0, b0);
        gemm_kernel<1><<<dim3(32, NSPLIT), 256>>>(emb, Wx1, Wh1, b1);
        cell_kernel<<<(RR * HH / 4 + 255) / 256, 256>>>(1, b1);
        gemm_kernel<2><<<dim3(125, 2), 256>>>(emb, Wout, Wout, bout);
        sample_kernel<<<RR, STH>>>(t, k0s0, k1s0, k0s1, k1s1, x, out);
    }
}